// round 5
// baseline (speedup 1.0000x reference)
#include <cuda_runtime.h>
#include <math_constants.h>

#define D 128
#define MAXN 50000
#define MAXE 800000

// -------- scratch (device globals: allocation-free contract) --------
__device__ float g_z[MAXN * D];       // projected features, current layer
__device__ float g_h[MAXN * D];       // layer output -> next layer input
__device__ float g_el[MAXN];
__device__ float g_er[MAXN];
__device__ float g_e[MAXE];           // per-edge scratch (fallback path only)
__device__ int   g_cnt[MAXN];         // in-degree histogram
__device__ int   g_off[MAXN + 1];     // CSR offsets by dst
__device__ int   g_woff[MAXN];        // scatter cursors
__device__ int   g_csr_src[MAXE];     // src node per CSR slot

// -------- helpers --------
__device__ __forceinline__ unsigned long long pack2(float f) {
    unsigned long long r;
    asm("mov.b64 %0, {%1, %1};" : "=l"(r) : "f"(f));
    return r;
}
__device__ __forceinline__ unsigned long long fma2(unsigned long long a,
                                                   unsigned long long b,
                                                   unsigned long long c) {
    unsigned long long d;
    asm("fma.rn.f32x2 %0, %1, %2, %3;" : "=l"(d) : "l"(a), "l"(b), "l"(c));
    return d;
}
__device__ __forceinline__ void unpack2(unsigned long long v, float& lo, float& hi) {
    asm("mov.b64 {%0, %1}, %2;" : "=f"(lo), "=f"(hi) : "l"(v));
}

// ================= CSR build (once per launch; graph shared by all layers) ==

__global__ void k_zcnt(int n) {
    int i = blockIdx.x * blockDim.x + threadIdx.x;
    if (i < n) g_cnt[i] = 0;
}

// 4 edges per thread (int4) for MLP
__global__ void k_hist(const int* __restrict__ dst, int eN) {
    int i = blockIdx.x * blockDim.x + threadIdx.x;
    int base = i * 4;
    if (base + 3 < eN) {
        int4 d4 = *(const int4*)&dst[base];
        atomicAdd(&g_cnt[d4.x], 1);
        atomicAdd(&g_cnt[d4.y], 1);
        atomicAdd(&g_cnt[d4.z], 1);
        atomicAdd(&g_cnt[d4.w], 1);
    } else {
        for (int j = base; j < eN; j++) atomicAdd(&g_cnt[dst[j]], 1);
    }
}

// single-block exclusive scan of g_cnt -> g_off / g_woff
__global__ __launch_bounds__(1024) void k_scan(int n, int eN) {
    __shared__ int part[1024];
    int t = threadIdx.x;
    int chunk = (n + 1023) / 1024;
    int lo = t * chunk;
    int hi = lo + chunk; if (hi > n) hi = n; if (lo > n) lo = n;
    int s = 0;
    for (int i = lo; i < hi; i++) s += g_cnt[i];
    part[t] = s;
    __syncthreads();
    for (int off = 1; off < 1024; off <<= 1) {
        int v = (t >= off) ? part[t - off] : 0;
        __syncthreads();
        part[t] += v;
        __syncthreads();
    }
    int run = (t == 0) ? 0 : part[t - 1];
    for (int i = lo; i < hi; i++) {
        g_off[i] = run; g_woff[i] = run;
        run += g_cnt[i];
    }
    if (t == 0) g_off[n] = eN;
}

__global__ void k_scatter(const int* __restrict__ src, const int* __restrict__ dst, int eN) {
    int i = blockIdx.x * blockDim.x + threadIdx.x;
    int base = i * 4;
    if (base + 3 < eN) {
        int4 s4 = *(const int4*)&src[base];
        int4 d4 = *(const int4*)&dst[base];
        int p0 = atomicAdd(&g_woff[d4.x], 1);
        int p1 = atomicAdd(&g_woff[d4.y], 1);
        int p2 = atomicAdd(&g_woff[d4.z], 1);
        int p3 = atomicAdd(&g_woff[d4.w], 1);
        g_csr_src[p0] = s4.x; g_csr_src[p1] = s4.y;
        g_csr_src[p2] = s4.z; g_csr_src[p3] = s4.w;
    } else {
        for (int j = base; j < eN; j++) {
            int pos = atomicAdd(&g_woff[dst[j]], 1);
            g_csr_src[pos] = src[j];
        }
    }
}

// ================= GEMM (z = x@W) with fused attention dot products =========
// Block tile 128 rows x 128 cols, 256 threads, 8x8 outputs/thread (f32x2 pairs
// over column pairs). x rows pre-packed as duplicated f32x2 in smem.
__global__ __launch_bounds__(256, 2) void k_gemm(const float* __restrict__ xin,
                                                 const float* __restrict__ W,
                                                 const float* __restrict__ al,
                                                 const float* __restrict__ ar, int n) {
    const float* x = xin ? xin : g_h;
    __shared__ unsigned long long xp2[128][32];   // [row][k] duplicated pairs (32KB)
    __shared__ float ws[32][128];                 // [k][col] (16KB)
    int tx = threadIdx.x;
    int row0 = blockIdx.x * 128;
    int c8 = tx & 15;        // 16 col-groups of 8 cols
    int rg = tx >> 4;        // 16 row-groups of 8 rows
    unsigned long long acc[8][4];
#pragma unroll
    for (int r = 0; r < 8; r++)
#pragma unroll
        for (int p = 0; p < 4; p++) acc[r][p] = 0ull;

    for (int k0 = 0; k0 < D; k0 += 32) {
        // ---- load 128x32 x-chunk as duplicated pairs ----
#pragma unroll
        for (int it = 0; it < 2; it++) {
            int t = it * 512 + tx * 2;            // process 2 float4 per it
#pragma unroll
            for (int u = 0; u < 2; u++) {
                int tt = t + u;                   // 0..1023
                int r = tt >> 3, kq = tt & 7;
                int grow = row0 + r;
                float4 v = make_float4(0.f, 0.f, 0.f, 0.f);
                if (grow < n) v = *(const float4*)&x[grow * D + k0 + kq * 4];
                // rotated store order: lanes kq>=4 store 1,2,3,0 -> conflict-free
                if (kq & 4) {
                    xp2[r][kq * 4 + 1] = pack2(v.y);
                    xp2[r][kq * 4 + 2] = pack2(v.z);
                    xp2[r][kq * 4 + 3] = pack2(v.w);
                    xp2[r][kq * 4 + 0] = pack2(v.x);
                } else {
                    xp2[r][kq * 4 + 0] = pack2(v.x);
                    xp2[r][kq * 4 + 1] = pack2(v.y);
                    xp2[r][kq * 4 + 2] = pack2(v.z);
                    xp2[r][kq * 4 + 3] = pack2(v.w);
                }
            }
        }
        // ---- load 32x128 W-chunk ----
#pragma unroll
        for (int it = 0; it < 4; it++) {
            int t = it * 256 + tx;                // 0..1023
            int kr = t >> 5, jq = t & 31;
            *(float4*)&ws[kr][jq * 4] = *(const float4*)&W[(k0 + kr) * D + jq * 4];
        }
        __syncthreads();
        // ---- compute: process k in pairs (vectorized x loads) ----
#pragma unroll
        for (int kk2 = 0; kk2 < 16; kk2++) {
            int kk = kk2 * 2;
            ulonglong2 xv[8];
#pragma unroll
            for (int r = 0; r < 8; r++)
                xv[r] = *(const ulonglong2*)&xp2[rg * 8 + r][kk];
            // k = kk
            {
                ulonglong2 wa = *(const ulonglong2*)&ws[kk][c8 * 8];
                ulonglong2 wb = *(const ulonglong2*)&ws[kk][c8 * 8 + 4];
#pragma unroll
                for (int r = 0; r < 8; r++) {
                    acc[r][0] = fma2(xv[r].x, wa.x, acc[r][0]);
                    acc[r][1] = fma2(xv[r].x, wa.y, acc[r][1]);
                    acc[r][2] = fma2(xv[r].x, wb.x, acc[r][2]);
                    acc[r][3] = fma2(xv[r].x, wb.y, acc[r][3]);
                }
            }
            // k = kk+1
            {
                ulonglong2 wa = *(const ulonglong2*)&ws[kk + 1][c8 * 8];
                ulonglong2 wb = *(const ulonglong2*)&ws[kk + 1][c8 * 8 + 4];
#pragma unroll
                for (int r = 0; r < 8; r++) {
                    acc[r][0] = fma2(xv[r].y, wa.x, acc[r][0]);
                    acc[r][1] = fma2(xv[r].y, wa.y, acc[r][1]);
                    acc[r][2] = fma2(xv[r].y, wb.x, acc[r][2]);
                    acc[r][3] = fma2(xv[r].y, wb.y, acc[r][3]);
                }
            }
        }
        __syncthreads();
    }

    // ---- epilogue: store z, fused el/er dots (16-thread reduction) ----
    float4 a0 = *(const float4*)&al[c8 * 8];
    float4 a1 = *(const float4*)&al[c8 * 8 + 4];
    float4 r0v = *(const float4*)&ar[c8 * 8];
    float4 r1v = *(const float4*)&ar[c8 * 8 + 4];
#pragma unroll
    for (int r = 0; r < 8; r++) {
        int row = row0 + rg * 8 + r;
        float c[8];
#pragma unroll
        for (int p = 0; p < 4; p++) unpack2(acc[r][p], c[2 * p], c[2 * p + 1]);
        if (row < n) {
            *(float4*)&g_z[row * D + c8 * 8]     = make_float4(c[0], c[1], c[2], c[3]);
            *(float4*)&g_z[row * D + c8 * 8 + 4] = make_float4(c[4], c[5], c[6], c[7]);
        }
        float el = c[0]*a0.x + c[1]*a0.y + c[2]*a0.z + c[3]*a0.w
                 + c[4]*a1.x + c[5]*a1.y + c[6]*a1.z + c[7]*a1.w;
        float er = c[0]*r0v.x + c[1]*r0v.y + c[2]*r0v.z + c[3]*r0v.w
                 + c[4]*r1v.x + c[5]*r1v.y + c[6]*r1v.z + c[7]*r1v.w;
#pragma unroll
        for (int o = 8; o > 0; o >>= 1) {
            el += __shfl_xor_sync(0xffffffffu, el, o, 16);
            er += __shfl_xor_sync(0xffffffffu, er, o, 16);
        }
        if (c8 == 0 && row < n) { g_el[row] = el; g_er[row] = er; }
    }
}

// ===== Fused per-dst softmax + aggregate + bias + ReLU (one warp per dst) ===
__global__ __launch_bounds__(256) void k_edge(const float* __restrict__ b,
                                              float* __restrict__ hout, int n) {
    int d = (blockIdx.x * blockDim.x + threadIdx.x) >> 5;
    int lane = threadIdx.x & 31;
    if (d >= n) return;
    int r0 = g_off[d];
    int deg = g_off[d + 1] - r0;
    float4 acc = make_float4(0.f, 0.f, 0.f, 0.f);

    if (deg > 0 && deg <= 128) {
        float erd = g_er[d];
        int   s[4];
        float ex[4];
        float m = -CUDART_INF_F;
#pragma unroll
        for (int c = 0; c < 4; c++) {
            int idx = c * 32 + lane;
            s[c] = 0; ex[c] = -CUDART_INF_F;
            if (idx < deg) {
                s[c] = g_csr_src[r0 + idx];
                float e = g_el[s[c]] + erd;
                e = e > 0.f ? e : 0.2f * e;
                ex[c] = e;
                m = fmaxf(m, e);
            }
        }
#pragma unroll
        for (int o = 16; o > 0; o >>= 1)
            m = fmaxf(m, __shfl_xor_sync(0xffffffffu, m, o));
        float ssum = 0.f;
#pragma unroll
        for (int c = 0; c < 4; c++) {
            if (c * 32 + lane < deg) {
                ex[c] = __expf(ex[c] - m);
                ssum += ex[c];
            }
        }
#pragma unroll
        for (int o = 16; o > 0; o >>= 1)
            ssum += __shfl_xor_sync(0xffffffffu, ssum, o);
        float inv = 1.0f / ssum;
#pragma unroll
        for (int c = 0; c < 4; c++) {
            if (c * 32 < deg) {
                int lim = deg - c * 32; if (lim > 32) lim = 32;
                for (int j = 0; j < lim; j++) {
                    int   sj = __shfl_sync(0xffffffffu, s[c], j);
                    float a  = __shfl_sync(0xffffffffu, ex[c], j) * inv;
                    float4 zv = *(const float4*)&g_z[(size_t)sj * D + lane * 4];
                    acc.x = fmaf(a, zv.x, acc.x);
                    acc.y = fmaf(a, zv.y, acc.y);
                    acc.z = fmaf(a, zv.z, acc.z);
                    acc.w = fmaf(a, zv.w, acc.w);
                }
            }
        }
    } else if (deg > 128) {
        // fallback: 3-pass via g_e (rare high-degree nodes)
        float erd = g_er[d];
        float m = -CUDART_INF_F;
        for (int i = lane; i < deg; i += 32) {
            int s = g_csr_src[r0 + i];
            float e = g_el[s] + erd;
            e = e > 0.f ? e : 0.2f * e;
            g_e[r0 + i] = e;
            m = fmaxf(m, e);
        }
#pragma unroll
        for (int o = 16; o > 0; o >>= 1)
            m = fmaxf(m, __shfl_xor_sync(0xffffffffu, m, o));
        float ssum = 0.f;
        for (int i = lane; i < deg; i += 32) {
            float ex = __expf(g_e[r0 + i] - m);
            g_e[r0 + i] = ex;
            ssum += ex;
        }
#pragma unroll
        for (int o = 16; o > 0; o >>= 1)
            ssum += __shfl_xor_sync(0xffffffffu, ssum, o);
        float inv = 1.0f / ssum;
        for (int c = 0; c < deg; c += 32) {
            int idx = c + lane;
            int   sl = 0; float exl = 0.f;
            if (idx < deg) { sl = g_csr_src[r0 + idx]; exl = g_e[r0 + idx]; }
            int lim = deg - c; if (lim > 32) lim = 32;
            for (int j = 0; j < lim; j++) {
                int   sj = __shfl_sync(0xffffffffu, sl, j);
                float a  = __shfl_sync(0xffffffffu, exl, j) * inv;
                float4 zv = *(const float4*)&g_z[(size_t)sj * D + lane * 4];
                acc.x = fmaf(a, zv.x, acc.x);
                acc.y = fmaf(a, zv.y, acc.y);
                acc.z = fmaf(a, zv.z, acc.z);
                acc.w = fmaf(a, zv.w, acc.w);
            }
        }
    }
    float4 bv = *(const float4*)&b[lane * 4];
    float4 o;
    o.x = fmaxf(acc.x + bv.x, 0.f);
    o.y = fmaxf(acc.y + bv.y, 0.f);
    o.z = fmaxf(acc.z + bv.z, 0.f);
    o.w = fmaxf(acc.w + bv.w, 0.f);
    float* out = hout ? hout : g_h;
    *(float4*)&out[d * D + lane * 4] = o;
}

// -------- launch --------
extern "C" void kernel_launch(void* const* d_in, const int* in_sizes, int n_in,
                              void* d_out, int out_size) {
    const float* f   = (const float*)d_in[0];
    const int*   src = (const int*)d_in[1];
    const int*   dst = (const int*)d_in[2];
    const float* W[3]  = { (const float*)d_in[3], (const float*)d_in[7],  (const float*)d_in[11] };
    const float* al[3] = { (const float*)d_in[4], (const float*)d_in[8],  (const float*)d_in[12] };
    const float* ar[3] = { (const float*)d_in[5], (const float*)d_in[9],  (const float*)d_in[13] };
    const float* bb[3] = { (const float*)d_in[6], (const float*)d_in[10], (const float*)d_in[14] };

    int n  = in_sizes[0] / D;
    int eN = in_sizes[1];
    float* out = (float*)d_out;

    // CSR by dst — graph is shared across the 3 layers
    int e4 = (eN + 3) / 4;
    k_zcnt   <<<(n + 255) / 256, 256>>>(n);
    k_hist   <<<(e4 + 255) / 256, 256>>>(dst, eN);
    k_scan   <<<1, 1024>>>(n, eN);
    k_scatter<<<(e4 + 255) / 256, 256>>>(src, dst, eN);

    for (int L = 0; L < 3; L++) {
        const float* xin = (L == 0) ? f : nullptr;    // nullptr -> read g_h
        float* hout = (L == 2) ? out : nullptr;       // nullptr -> write g_h
        k_gemm<<<(n + 127) / 128, 256>>>(xin, W[L], al[L], ar[L], n);
        k_edge<<<(n + 7) / 8, 256>>>(bb[L], hout, n);
    }
}

// round 6
// speedup vs baseline: 1.1292x; 1.1292x over previous
#include <cuda_runtime.h>
#include <math_constants.h>

#define D 128
#define MAXN 50000
#define MAXE 800000

// -------- scratch (device globals: allocation-free contract) --------
__device__ float g_z[MAXN * D];       // projected features, current layer
__device__ float g_h[MAXN * D];       // layer output -> next layer input
__device__ float g_el[MAXN];
__device__ float g_er[MAXN];
__device__ float g_e[MAXE];           // per-edge scratch (fallback path only)
__device__ int   g_cnt[MAXN];         // in-degree histogram
__device__ int   g_off[MAXN + 1];     // CSR offsets by dst
__device__ int   g_woff[MAXN];        // scatter cursors
__device__ int   g_csr_src[MAXE];     // src node per CSR slot

// -------- helpers --------
__device__ __forceinline__ unsigned long long pack2(float f) {
    unsigned long long r;
    asm("mov.b64 %0, {%1, %1};" : "=l"(r) : "f"(f));
    return r;
}
__device__ __forceinline__ unsigned long long fma2(unsigned long long a,
                                                   unsigned long long b,
                                                   unsigned long long c) {
    unsigned long long d;
    asm("fma.rn.f32x2 %0, %1, %2, %3;" : "=l"(d) : "l"(a), "l"(b), "l"(c));
    return d;
}
__device__ __forceinline__ void unpack2(unsigned long long v, float& lo, float& hi) {
    asm("mov.b64 {%0, %1}, %2;" : "=f"(lo), "=f"(hi) : "l"(v));
}

// ================= CSR build (once per launch; graph shared by all layers) ==

__global__ void k_zcnt(int n) {
    int i = blockIdx.x * blockDim.x + threadIdx.x;
    if (i < n) g_cnt[i] = 0;
}

__global__ void k_hist(const int* __restrict__ dst, int eN) {
    int i = blockIdx.x * blockDim.x + threadIdx.x;
    if (i < eN) atomicAdd(&g_cnt[dst[i]], 1);
}

// single-block exclusive scan of g_cnt -> g_off / g_woff
__global__ __launch_bounds__(1024) void k_scan(int n, int eN) {
    __shared__ int part[1024];
    int t = threadIdx.x;
    int chunk = (n + 1023) / 1024;
    int lo = t * chunk;
    int hi = lo + chunk; if (hi > n) hi = n; if (lo > n) lo = n;
    int s = 0;
    for (int i = lo; i < hi; i++) s += g_cnt[i];
    part[t] = s;
    __syncthreads();
    for (int off = 1; off < 1024; off <<= 1) {
        int v = (t >= off) ? part[t - off] : 0;
        __syncthreads();
        part[t] += v;
        __syncthreads();
    }
    int run = (t == 0) ? 0 : part[t - 1];
    for (int i = lo; i < hi; i++) {
        g_off[i] = run; g_woff[i] = run;
        run += g_cnt[i];
    }
    if (t == 0) g_off[n] = eN;
}

__global__ void k_scatter(const int* __restrict__ src, const int* __restrict__ dst, int eN) {
    int i = blockIdx.x * blockDim.x + threadIdx.x;
    if (i >= eN) return;
    int pos = atomicAdd(&g_woff[dst[i]], 1);
    g_csr_src[pos] = src[i];
}

// ================= GEMM (z = x@W) with fused attention dot products =========
// R3 configuration: block tile 64 rows x 128 cols, 256 threads, f32x2 FMA.
__global__ __launch_bounds__(256) void k_gemm(const float* __restrict__ xin,
                                              const float* __restrict__ W,
                                              const float* __restrict__ al,
                                              const float* __restrict__ ar, int n) {
    const float* x = xin ? xin : g_h;
    __shared__ float xt[32][66];
    __shared__ float ws[32][128];
    int tx = threadIdx.x;
    int row0 = blockIdx.x * 64;
    int c4 = tx & 31;
    int rg = tx >> 5;
    unsigned long long acc[4][4];
#pragma unroll
    for (int rp = 0; rp < 4; rp++)
#pragma unroll
        for (int c = 0; c < 4; c++) acc[rp][c] = 0ull;

    for (int k0 = 0; k0 < D; k0 += 32) {
#pragma unroll
        for (int it = 0; it < 2; it++) {
            int t = it * 256 + tx;
            int r = t >> 3, kq = t & 7;
            int grow = row0 + r;
            float4 v = make_float4(0.f, 0.f, 0.f, 0.f);
            if (grow < n) v = *(const float4*)&x[grow * D + k0 + kq * 4];
            xt[kq * 4 + 0][r] = v.x;
            xt[kq * 4 + 1][r] = v.y;
            xt[kq * 4 + 2][r] = v.z;
            xt[kq * 4 + 3][r] = v.w;
        }
#pragma unroll
        for (int it = 0; it < 4; it++) {
            int t = it * 256 + tx;
            int kr = t >> 5, jq = t & 31;
            *(float4*)&ws[kr][jq * 4] = *(const float4*)&W[(k0 + kr) * D + jq * 4];
        }
        __syncthreads();
#pragma unroll
        for (int kk = 0; kk < 32; kk++) {
            float4 wv = *(const float4*)&ws[kk][c4 * 4];
            unsigned long long w2[4];
            w2[0] = pack2(wv.x); w2[1] = pack2(wv.y);
            w2[2] = pack2(wv.z); w2[3] = pack2(wv.w);
#pragma unroll
            for (int rp = 0; rp < 4; rp++) {
                unsigned long long xp =
                    *(const unsigned long long*)&xt[kk][rg * 8 + rp * 2];
                acc[rp][0] = fma2(xp, w2[0], acc[rp][0]);
                acc[rp][1] = fma2(xp, w2[1], acc[rp][1]);
                acc[rp][2] = fma2(xp, w2[2], acc[rp][2]);
                acc[rp][3] = fma2(xp, w2[3], acc[rp][3]);
            }
        }
        __syncthreads();
    }

    float4 alv = *(const float4*)&al[c4 * 4];
    float4 arv = *(const float4*)&ar[c4 * 4];
#pragma unroll
    for (int rp = 0; rp < 4; rp++) {
        int r = row0 + rg * 8 + rp * 2;
        float lo[4], hi[4];
#pragma unroll
        for (int c = 0; c < 4; c++) unpack2(acc[rp][c], lo[c], hi[c]);
        if (r < n)
            *(float4*)&g_z[r * D + c4 * 4] = make_float4(lo[0], lo[1], lo[2], lo[3]);
        if (r + 1 < n)
            *(float4*)&g_z[(r + 1) * D + c4 * 4] = make_float4(hi[0], hi[1], hi[2], hi[3]);
        float el_lo = lo[0]*alv.x + lo[1]*alv.y + lo[2]*alv.z + lo[3]*alv.w;
        float er_lo = lo[0]*arv.x + lo[1]*arv.y + lo[2]*arv.z + lo[3]*arv.w;
        float el_hi = hi[0]*alv.x + hi[1]*alv.y + hi[2]*alv.z + hi[3]*alv.w;
        float er_hi = hi[0]*arv.x + hi[1]*arv.y + hi[2]*arv.z + hi[3]*arv.w;
#pragma unroll
        for (int o = 16; o > 0; o >>= 1) {
            el_lo += __shfl_xor_sync(0xffffffffu, el_lo, o);
            er_lo += __shfl_xor_sync(0xffffffffu, er_lo, o);
            el_hi += __shfl_xor_sync(0xffffffffu, el_hi, o);
            er_hi += __shfl_xor_sync(0xffffffffu, er_hi, o);
        }
        if (c4 == 0) {
            if (r < n)     { g_el[r] = el_lo;     g_er[r] = er_lo; }
            if (r + 1 < n) { g_el[r + 1] = el_hi; g_er[r + 1] = er_hi; }
        }
    }
}

// ===== Fused per-dst softmax + aggregate + bias + ReLU (one warp per dst) ===
// Register-resident edge list (deg<=128), deferred normalization, 2-way MLP.
__global__ __launch_bounds__(256) void k_edge(const float* __restrict__ b,
                                              float* __restrict__ hout, int n) {
    int d = (blockIdx.x * blockDim.x + threadIdx.x) >> 5;
    int lane = threadIdx.x & 31;
    if (d >= n) return;
    int r0 = g_off[d];
    int deg = g_off[d + 1] - r0;
    float4 acc  = make_float4(0.f, 0.f, 0.f, 0.f);
    float4 acc2 = make_float4(0.f, 0.f, 0.f, 0.f);
    float inv = 0.f;

    if (deg > 0 && deg <= 128) {
        float erd = g_er[d];
        int   s[4];
        float ex[4];
        float m = -CUDART_INF_F;
#pragma unroll
        for (int c = 0; c < 4; c++) {
            int idx = c * 32 + lane;
            s[c] = 0; ex[c] = -CUDART_INF_F;
            if (idx < deg) {
                s[c] = g_csr_src[r0 + idx];
                float e = g_el[s[c]] + erd;
                e = e > 0.f ? e : 0.2f * e;
                ex[c] = e;
                m = fmaxf(m, e);
            }
        }
#pragma unroll
        for (int o = 16; o > 0; o >>= 1)
            m = fmaxf(m, __shfl_xor_sync(0xffffffffu, m, o));
        float ssum = 0.f;
#pragma unroll
        for (int c = 0; c < 4; c++) {
            if (c * 32 + lane < deg) {
                ex[c] = __expf(ex[c] - m);
                ssum += ex[c];
            }
        }
#pragma unroll
        for (int o = 16; o > 0; o >>= 1)
            ssum += __shfl_xor_sync(0xffffffffu, ssum, o);
        inv = 1.0f / ssum;
        // gather: acc = sum(ex_j * z[src_j]); normalize once at the end
#pragma unroll
        for (int c = 0; c < 4; c++) {
            if (c * 32 < deg) {
                int lim = deg - c * 32; if (lim > 32) lim = 32;
                int j = 0;
                for (; j + 1 < lim; j += 2) {
                    int   s0 = __shfl_sync(0xffffffffu, s[c], j);
                    float a0 = __shfl_sync(0xffffffffu, ex[c], j);
                    int   s1 = __shfl_sync(0xffffffffu, s[c], j + 1);
                    float a1 = __shfl_sync(0xffffffffu, ex[c], j + 1);
                    float4 z0 = *(const float4*)&g_z[(size_t)s0 * D + lane * 4];
                    float4 z1 = *(const float4*)&g_z[(size_t)s1 * D + lane * 4];
                    acc.x  = fmaf(a0, z0.x, acc.x);
                    acc.y  = fmaf(a0, z0.y, acc.y);
                    acc.z  = fmaf(a0, z0.z, acc.z);
                    acc.w  = fmaf(a0, z0.w, acc.w);
                    acc2.x = fmaf(a1, z1.x, acc2.x);
                    acc2.y = fmaf(a1, z1.y, acc2.y);
                    acc2.z = fmaf(a1, z1.z, acc2.z);
                    acc2.w = fmaf(a1, z1.w, acc2.w);
                }
                if (j < lim) {
                    int   s0 = __shfl_sync(0xffffffffu, s[c], j);
                    float a0 = __shfl_sync(0xffffffffu, ex[c], j);
                    float4 z0 = *(const float4*)&g_z[(size_t)s0 * D + lane * 4];
                    acc.x = fmaf(a0, z0.x, acc.x);
                    acc.y = fmaf(a0, z0.y, acc.y);
                    acc.z = fmaf(a0, z0.z, acc.z);
                    acc.w = fmaf(a0, z0.w, acc.w);
                }
            }
        }
    } else if (deg > 128) {
        // fallback: 3-pass via g_e (rare high-degree nodes)
        float erd = g_er[d];
        float m = -CUDART_INF_F;
        for (int i = lane; i < deg; i += 32) {
            int s = g_csr_src[r0 + i];
            float e = g_el[s] + erd;
            e = e > 0.f ? e : 0.2f * e;
            g_e[r0 + i] = e;
            m = fmaxf(m, e);
        }
#pragma unroll
        for (int o = 16; o > 0; o >>= 1)
            m = fmaxf(m, __shfl_xor_sync(0xffffffffu, m, o));
        float ssum = 0.f;
        for (int i = lane; i < deg; i += 32) {
            float ex = __expf(g_e[r0 + i] - m);
            g_e[r0 + i] = ex;
            ssum += ex;
        }
#pragma unroll
        for (int o = 16; o > 0; o >>= 1)
            ssum += __shfl_xor_sync(0xffffffffu, ssum, o);
        inv = 1.0f / ssum;
        for (int c = 0; c < deg; c += 32) {
            int idx = c + lane;
            int   sl = 0; float exl = 0.f;
            if (idx < deg) { sl = g_csr_src[r0 + idx]; exl = g_e[r0 + idx]; }
            int lim = deg - c; if (lim > 32) lim = 32;
            for (int j = 0; j < lim; j++) {
                int   sj = __shfl_sync(0xffffffffu, sl, j);
                float a  = __shfl_sync(0xffffffffu, exl, j);
                float4 zv = *(const float4*)&g_z[(size_t)sj * D + lane * 4];
                acc.x = fmaf(a, zv.x, acc.x);
                acc.y = fmaf(a, zv.y, acc.y);
                acc.z = fmaf(a, zv.z, acc.z);
                acc.w = fmaf(a, zv.w, acc.w);
            }
        }
    }
    float4 bv = *(const float4*)&b[lane * 4];
    float4 o;
    o.x = fmaxf(fmaf(acc.x + acc2.x, inv, bv.x), 0.f);
    o.y = fmaxf(fmaf(acc.y + acc2.y, inv, bv.y), 0.f);
    o.z = fmaxf(fmaf(acc.z + acc2.z, inv, bv.z), 0.f);
    o.w = fmaxf(fmaf(acc.w + acc2.w, inv, bv.w), 0.f);
    float* out = hout ? hout : g_h;
    *(float4*)&out[d * D + lane * 4] = o;
}

// -------- launch --------
extern "C" void kernel_launch(void* const* d_in, const int* in_sizes, int n_in,
                              void* d_out, int out_size) {
    const float* f   = (const float*)d_in[0];
    const int*   src = (const int*)d_in[1];
    const int*   dst = (const int*)d_in[2];
    const float* W[3]  = { (const float*)d_in[3], (const float*)d_in[7],  (const float*)d_in[11] };
    const float* al[3] = { (const float*)d_in[4], (const float*)d_in[8],  (const float*)d_in[12] };
    const float* ar[3] = { (const float*)d_in[5], (const float*)d_in[9],  (const float*)d_in[13] };
    const float* bb[3] = { (const float*)d_in[6], (const float*)d_in[10], (const float*)d_in[14] };

    int n  = in_sizes[0] / D;
    int eN = in_sizes[1];
    float* out = (float*)d_out;

    // One side stream + fork/join events (created once; deterministic work).
    static cudaStream_t s2 = nullptr;
    static cudaEvent_t evFork = nullptr, evJoin = nullptr;
    if (!s2) {
        cudaStreamCreateWithFlags(&s2, cudaStreamNonBlocking);
        cudaEventCreateWithFlags(&evFork, cudaEventDisableTiming);
        cudaEventCreateWithFlags(&evJoin, cudaEventDisableTiming);
    }

    // Fork: CSR build on s2, concurrent with layer-1 GEMM on the main stream.
    cudaEventRecord(evFork, 0);
    cudaStreamWaitEvent(s2, evFork, 0);
    k_zcnt   <<<(n + 255) / 256, 256, 0, s2>>>(n);
    k_hist   <<<(eN + 255) / 256, 256, 0, s2>>>(dst, eN);
    k_scan   <<<1, 1024, 0, s2>>>(n, eN);
    k_scatter<<<(eN + 255) / 256, 256, 0, s2>>>(src, dst, eN);
    cudaEventRecord(evJoin, s2);

    k_gemm<<<(n + 63) / 64, 256>>>(f, W[0], al[0], ar[0], n);

    // Join: edge-1 needs both GEMM-1 and the CSR.
    cudaStreamWaitEvent(0, evJoin, 0);

    k_edge<<<(n + 7) / 8, 256>>>(bb[0], nullptr, n);

    for (int L = 1; L < 3; L++) {
        float* hout = (L == 2) ? out : nullptr;
        k_gemm<<<(n + 63) / 64, 256>>>(nullptr, W[L], al[L], ar[L], n);
        k_edge<<<(n + 7) / 8, 256>>>(bb[L], hout, n);
    }
}

// round 9
// speedup vs baseline: 1.1900x; 1.0539x over previous
#include <cuda_runtime.h>
#include <cuda_bf16.h>
#include <math_constants.h>
#include <cstdint>

#define D 128
#define MAXN 50000
#define MAXE 800000

// -------- scratch (device globals: allocation-free contract) --------
__device__ float g_z[MAXN * D];       // projected features, current layer
__device__ float g_h[MAXN * D];       // layer output -> next layer input
__device__ float g_el[MAXN];
__device__ float g_er[MAXN];
__device__ float g_e[MAXE];           // per-edge scratch (fallback path only)
__device__ int   g_cnt[MAXN];
__device__ int   g_off[MAXN + 1];
__device__ int   g_woff[MAXN];
__device__ int   g_csr_src[MAXE];
__device__ __nv_bfloat16 g_wh[3][D * D];   // W^T hi split, [n][k] K-major
__device__ __nv_bfloat16 g_wl[3][D * D];   // W^T lo split

// ================= CSR build ================================================

__global__ void k_zcnt(int n) {
    int i = blockIdx.x * blockDim.x + threadIdx.x;
    if (i < n) g_cnt[i] = 0;
}
__global__ void k_hist(const int* __restrict__ dst, int eN) {
    int i = blockIdx.x * blockDim.x + threadIdx.x;
    if (i < eN) atomicAdd(&g_cnt[dst[i]], 1);
}
__global__ __launch_bounds__(1024) void k_scan(int n, int eN) {
    __shared__ int part[1024];
    int t = threadIdx.x;
    int chunk = (n + 1023) / 1024;
    int lo = t * chunk;
    int hi = lo + chunk; if (hi > n) hi = n; if (lo > n) lo = n;
    int s = 0;
    for (int i = lo; i < hi; i++) s += g_cnt[i];
    part[t] = s;
    __syncthreads();
    for (int off = 1; off < 1024; off <<= 1) {
        int v = (t >= off) ? part[t - off] : 0;
        __syncthreads();
        part[t] += v;
        __syncthreads();
    }
    int run = (t == 0) ? 0 : part[t - 1];
    for (int i = lo; i < hi; i++) {
        g_off[i] = run; g_woff[i] = run;
        run += g_cnt[i];
    }
    if (t == 0) g_off[n] = eN;
}
__global__ void k_scatter(const int* __restrict__ src, const int* __restrict__ dst, int eN) {
    int i = blockIdx.x * blockDim.x + threadIdx.x;
    if (i >= eN) return;
    int pos = atomicAdd(&g_woff[dst[i]], 1);
    g_csr_src[pos] = src[i];
}

// ========== W split: W -> W^T bf16 hi/lo, [n][k] K-major (once per layer) ===
__global__ void k_wsplit(const float* __restrict__ W, int L) {
    __shared__ float t[32][33];
    int bx = blockIdx.x, by = blockIdx.y;
    int txx = threadIdx.x, tyy = threadIdx.y;
    t[tyy][txx] = W[(by * 32 + tyy) * D + bx * 32 + txx];
    __syncthreads();
    int n2 = bx * 32 + tyy, k2 = by * 32 + txx;
    float v = t[txx][tyy];
    __nv_bfloat16 hi = __float2bfloat16_rn(v);
    float lo = v - __bfloat162float(hi);
    g_wh[L][n2 * D + k2] = hi;
    g_wl[L][n2 * D + k2] = __float2bfloat16_rn(lo);
}

// ================= mma.sync bf16-split GEMM =================================
__device__ __forceinline__ void mma16816(float* c, uint32_t a0, uint32_t a1,
                                         uint32_t a2, uint32_t a3,
                                         uint32_t b0, uint32_t b1) {
    asm volatile(
        "mma.sync.aligned.m16n8k16.row.col.f32.bf16.bf16.f32 "
        "{%0,%1,%2,%3}, {%4,%5,%6,%7}, {%8,%9}, {%0,%1,%2,%3};"
        : "+f"(c[0]), "+f"(c[1]), "+f"(c[2]), "+f"(c[3])
        : "r"(a0), "r"(a1), "r"(a2), "r"(a3), "r"(b0), "r"(b1));
}
__device__ __forceinline__ uint32_t pack_bf2(float x, float y) {
    __nv_bfloat162 p = __float22bfloat162_rn(make_float2(x, y));
    return *(uint32_t*)&p;
}

#define SMS 136   // padded k-stride (bf16 elems): conflict-free fragment LDS

// z = x@W with fused el/er. CTA: 128 rows x 128 cols, 256 threads, 8 warps.
// Warp w: rows [w*16, w*16+16), all 128 cols. 3-way bf16 split via mma.sync.
__global__ __launch_bounds__(256) void k_gemm_mma(const float* __restrict__ xin,
                                                  int L,
                                                  const float* __restrict__ al,
                                                  const float* __restrict__ ar,
                                                  int n) {
    extern __shared__ char smem[];
    __nv_bfloat16* sA0 = (__nv_bfloat16*)smem;          // x hi [128][SMS]
    __nv_bfloat16* sA1 = sA0 + 128 * SMS;               // x lo
    __nv_bfloat16* sB0 = sA1 + 128 * SMS;               // W^T hi [n][SMS]
    __nv_bfloat16* sB1 = sB0 + 128 * SMS;               // W^T lo
    float* sal = (float*)(sB1 + 128 * SMS);
    float* sar = sal + 128;

    const float* x = xin ? xin : g_h;
    int tx = threadIdx.x;
    int wid = tx >> 5, lane = tx & 31;
    int row0 = blockIdx.x * 128;

    if (tx < 128) { sal[tx] = al[tx]; sar[tx] = ar[tx]; }

    // ---- fill B: straight vector copy (row stride 128 -> SMS) ----
    {
        const __nv_bfloat16* wsrc = (tx < 128) ? g_wh[L] : g_wl[L];
        __nv_bfloat16* bd = (tx < 128) ? sB0 : sB1;
        int nn = tx & 127;
        const uint4* sv = (const uint4*)(wsrc + nn * D);
        uint4* dv = (uint4*)(bd + nn * SMS);
#pragma unroll
        for (int i = 0; i < 16; i++) dv[i] = sv[i];
    }
    // ---- fill A: convert fp32 -> bf16 hi/lo ----
    {
        int row = tx >> 1, h = tx & 1;
        int grow = row0 + row;
        const float4* xr = (const float4*)&x[(size_t)grow * D + h * 64];
#pragma unroll
        for (int j = 0; j < 16; j++) {
            float4 v = (grow < n) ? xr[j] : make_float4(0.f, 0.f, 0.f, 0.f);
            __nv_bfloat16 h0 = __float2bfloat16_rn(v.x);
            __nv_bfloat16 h1 = __float2bfloat16_rn(v.y);
            __nv_bfloat16 h2 = __float2bfloat16_rn(v.z);
            __nv_bfloat16 h3 = __float2bfloat16_rn(v.w);
            uint32_t hp0, hp1;
            { __nv_bfloat162 p = make_bfloat162(h0, h1); hp0 = *(uint32_t*)&p; }
            { __nv_bfloat162 p = make_bfloat162(h2, h3); hp1 = *(uint32_t*)&p; }
            uint32_t lp0 = pack_bf2(v.x - __bfloat162float(h0),
                                    v.y - __bfloat162float(h1));
            uint32_t lp1 = pack_bf2(v.z - __bfloat162float(h2),
                                    v.w - __bfloat162float(h3));
            int ko = h * 64 + j * 4;
            *(uint2*)&sA0[row * SMS + ko] = make_uint2(hp0, hp1);
            *(uint2*)&sA1[row * SMS + ko] = make_uint2(lp0, lp1);
        }
    }
    __syncthreads();

    // ---- compute ----
    int g = lane >> 2, q = lane & 3;
    int ra = wid * 16 + g;          // local rows ra, ra+8
    float acc[16][4];
#pragma unroll
    for (int nt = 0; nt < 16; nt++)
#pragma unroll
        for (int p = 0; p < 4; p++) acc[nt][p] = 0.f;

#pragma unroll
    for (int kc = 0; kc < 8; kc++) {
        int ka = kc * 16 + q * 2;
        uint32_t ah0 = *(const uint32_t*)&sA0[ra * SMS + ka];
        uint32_t ah1 = *(const uint32_t*)&sA0[(ra + 8) * SMS + ka];
        uint32_t ah2 = *(const uint32_t*)&sA0[ra * SMS + ka + 8];
        uint32_t ah3 = *(const uint32_t*)&sA0[(ra + 8) * SMS + ka + 8];
        uint32_t av0 = *(const uint32_t*)&sA1[ra * SMS + ka];
        uint32_t av1 = *(const uint32_t*)&sA1[(ra + 8) * SMS + ka];
        uint32_t av2 = *(const uint32_t*)&sA1[ra * SMS + ka + 8];
        uint32_t av3 = *(const uint32_t*)&sA1[(ra + 8) * SMS + ka + 8];
#pragma unroll
        for (int nt = 0; nt < 16; nt++) {
            int nb = nt * 8 + g;
            uint32_t bh0 = *(const uint32_t*)&sB0[nb * SMS + ka];
            uint32_t bh1 = *(const uint32_t*)&sB0[nb * SMS + ka + 8];
            uint32_t bl0 = *(const uint32_t*)&sB1[nb * SMS + ka];
            uint32_t bl1 = *(const uint32_t*)&sB1[nb * SMS + ka + 8];
            mma16816(acc[nt], ah0, ah1, ah2, ah3, bh0, bh1);   // hi*hi
            mma16816(acc[nt], ah0, ah1, ah2, ah3, bl0, bl1);   // hi*lo
            mma16816(acc[nt], av0, av1, av2, av3, bh0, bh1);   // lo*hi
        }
    }

    // ---- epilogue: z stores + fused el/er ----
    int r1 = row0 + ra, r2 = r1 + 8;
    float el1 = 0.f, er1 = 0.f, el2 = 0.f, er2 = 0.f;
#pragma unroll
    for (int nt = 0; nt < 16; nt++) {
        int c0 = nt * 8 + q * 2;
        float a0v = sal[c0], a1v = sal[c0 + 1];
        float r0v = sar[c0], r1v = sar[c0 + 1];
        el1 += acc[nt][0] * a0v + acc[nt][1] * a1v;
        er1 += acc[nt][0] * r0v + acc[nt][1] * r1v;
        el2 += acc[nt][2] * a0v + acc[nt][3] * a1v;
        er2 += acc[nt][2] * r0v + acc[nt][3] * r1v;
        if (r1 < n) *(float2*)&g_z[(size_t)r1 * D + c0] = make_float2(acc[nt][0], acc[nt][1]);
        if (r2 < n) *(float2*)&g_z[(size_t)r2 * D + c0] = make_float2(acc[nt][2], acc[nt][3]);
    }
#pragma unroll
    for (int o = 1; o <= 2; o <<= 1) {
        el1 += __shfl_xor_sync(0xffffffffu, el1, o);
        er1 += __shfl_xor_sync(0xffffffffu, er1, o);
        el2 += __shfl_xor_sync(0xffffffffu, el2, o);
        er2 += __shfl_xor_sync(0xffffffffu, er2, o);
    }
    if (q == 0) {
        if (r1 < n) { g_el[r1] = el1; g_er[r1] = er1; }
        if (r2 < n) { g_el[r2] = el2; g_er[r2] = er2; }
    }
}

#define GEMM_SMEM (4 * 128 * SMS * 2 + 2 * 128 * 4)

// ===== Fused per-dst softmax + aggregate + bias + ReLU (one warp per dst) ===
__global__ __launch_bounds__(256) void k_edge(const float* __restrict__ b,
                                              float* __restrict__ hout, int n) {
    int d = (blockIdx.x * blockDim.x + threadIdx.x) >> 5;
    int lane = threadIdx.x & 31;
    if (d >= n) return;
    int r0 = g_off[d];
    int deg = g_off[d + 1] - r0;
    float4 acc  = make_float4(0.f, 0.f, 0.f, 0.f);
    float4 acc2 = make_float4(0.f, 0.f, 0.f, 0.f);
    float inv = 0.f;

    if (deg > 0 && deg <= 128) {
        float erd = g_er[d];
        int   s[4];
        float ex[4];
        float m = -CUDART_INF_F;
#pragma unroll
        for (int c = 0; c < 4; c++) {
            int idx = c * 32 + lane;
            s[c] = 0; ex[c] = -CUDART_INF_F;
            if (idx < deg) {
                s[c] = g_csr_src[r0 + idx];
                float e = g_el[s[c]] + erd;
                e = e > 0.f ? e : 0.2f * e;
                ex[c] = e;
                m = fmaxf(m, e);
            }
        }
#pragma unroll
        for (int o = 16; o > 0; o >>= 1)
            m = fmaxf(m, __shfl_xor_sync(0xffffffffu, m, o));
        float ssum = 0.f;
#pragma unroll
        for (int c = 0; c < 4; c++) {
            if (c * 32 + lane < deg) {
                ex[c] = __expf(ex[c] - m);
                ssum += ex[c];
            }
        }
#pragma unroll
        for (int o = 16; o > 0; o >>= 1)
            ssum += __shfl_xor_sync(0xffffffffu, ssum, o);
        inv = 1.0f / ssum;
#pragma unroll
        for (int c = 0; c < 4; c++) {
            if (c * 32 < deg) {
                int lim = deg - c * 32; if (lim > 32) lim = 32;
                int j = 0;
                for (; j + 1 < lim; j += 2) {
                    int   s0 = __shfl_sync(0xffffffffu, s[c], j);
                    float a0 = __shfl_sync(0xffffffffu, ex[c], j);
                    int   s1 = __shfl_sync(0xffffffffu, s[c], j + 1);
                    float a1 = __shfl_sync(0xffffffffu, ex[c], j + 1);
                    float4 z0 = *(const float4*)&g_z[(size_t)s0 * D + lane * 4];
                    float4 z1 = *(const float4*)&g_z[(size_t)s1 * D + lane * 4];
                    acc.x  = fmaf(a0, z0.x, acc.x);
                    acc.y  = fmaf(a0, z0.y, acc.y);
                    acc.z  = fmaf(a0, z0.z, acc.z);
                    acc.w  = fmaf(a0, z0.w, acc.w);
                    acc2.x = fmaf(a1, z1.x, acc2.x);
                    acc2.y = fmaf(a1, z1.y, acc2.y);
                    acc2.z = fmaf(a1, z1.z, acc2.z);
                    acc2.w = fmaf(a1, z1.w, acc2.w);
                }
                if (j < lim) {
                    int   s0 = __shfl_sync(0xffffffffu, s[c], j);
                    float a0 = __shfl_sync(0xffffffffu, ex[c], j);
                    float4 z0 = *(const float4*)&g_z[(size_t)s0 * D + lane * 4];
                    acc.x = fmaf(a0, z0.x, acc.x);
                    acc.y = fmaf(a0, z0.y, acc.y);
                    acc.z = fmaf(a0, z0.z, acc.z);
                    acc.w = fmaf(a0, z0.w, acc.w);
                }
            }
        }
    } else if (deg > 128) {
        float erd = g_er[d];
        float m = -CUDART_INF_F;
        for (int i = lane; i < deg; i += 32) {
            int s = g_csr_src[r0 + i];
            float e = g_el[s] + erd;
            e = e > 0.f ? e : 0.2f * e;
            g_e[r0 + i] = e;
            m = fmaxf(m, e);
        }
#pragma unroll
        for (int o = 16; o > 0; o >>= 1)
            m = fmaxf(m, __shfl_xor_sync(0xffffffffu, m, o));
        float ssum = 0.f;
        for (int i = lane; i < deg; i += 32) {
            float ex = __expf(g_e[r0 + i] - m);
            g_e[r0 + i] = ex;
            ssum += ex;
        }
#pragma unroll
        for (int o = 16; o > 0; o >>= 1)
            ssum += __shfl_xor_sync(0xffffffffu, ssum, o);
        inv = 1.0f / ssum;
        for (int c = 0; c < deg; c += 32) {
            int idx = c + lane;
            int   sl = 0; float exl = 0.f;
            if (idx < deg) { sl = g_csr_src[r0 + idx]; exl = g_e[r0 + idx]; }
            int lim = deg - c; if (lim > 32) lim = 32;
            for (int j = 0; j < lim; j++) {
                int   sj = __shfl_sync(0xffffffffu, sl, j);
                float a  = __shfl_sync(0xffffffffu, exl, j);
                float4 zv = *(const float4*)&g_z[(size_t)sj * D + lane * 4];
                acc.x = fmaf(a, zv.x, acc.x);
                acc.y = fmaf(a, zv.y, acc.y);
                acc.z = fmaf(a, zv.z, acc.z);
                acc.w = fmaf(a, zv.w, acc.w);
            }
        }
    }
    float4 bv = *(const float4*)&b[lane * 4];
    float4 o;
    o.x = fmaxf(fmaf(acc.x + acc2.x, inv, bv.x), 0.f);
    o.y = fmaxf(fmaf(acc.y + acc2.y, inv, bv.y), 0.f);
    o.z = fmaxf(fmaf(acc.z + acc2.z, inv, bv.z), 0.f);
    o.w = fmaxf(fmaf(acc.w + acc2.w, inv, bv.w), 0.f);
    float* out = hout ? hout : g_h;
    *(float4*)&out[d * D + lane * 4] = o;
}

// -------- launch --------
extern "C" void kernel_launch(void* const* d_in, const int* in_sizes, int n_in,
                              void* d_out, int out_size) {
    const float* f   = (const float*)d_in[0];
    const int*   src = (const int*)d_in[1];
    const int*   dst = (const int*)d_in[2];
    const float* W[3]  = { (const float*)d_in[3], (const float*)d_in[7],  (const float*)d_in[11] };
    const float* al[3] = { (const float*)d_in[4], (const float*)d_in[8],  (const float*)d_in[12] };
    const float* ar[3] = { (const float*)d_in[5], (const float*)d_in[9],  (const float*)d_in[13] };
    const float* bb[3] = { (const float*)d_in[6], (const float*)d_in[10], (const float*)d_in[14] };

    int n  = in_sizes[0] / D;
    int eN = in_sizes[1];
    float* out = (float*)d_out;

    static bool init = false;
    if (!init) {
        cudaFuncSetAttribute(k_gemm_mma, cudaFuncAttributeMaxDynamicSharedMemorySize,
                             GEMM_SMEM);
        init = true;
    }

    // CSR build (graph shared across layers)
    k_zcnt   <<<(n + 255) / 256, 256>>>(n);
    k_hist   <<<(eN + 255) / 256, 256>>>(dst, eN);
    k_scan   <<<1, 1024>>>(n, eN);
    k_scatter<<<(eN + 255) / 256, 256>>>(src, dst, eN);

    // W hi/lo splits
    for (int L = 0; L < 3; L++)
        k_wsplit<<<dim3(4, 4), dim3(32, 32)>>>(W[L], L);

    int gemmGrid = (n + 127) / 128;
    for (int L = 0; L < 3; L++) {
        const float* xin = (L == 0) ? f : nullptr;
        float* hout = (L == 2) ? out : nullptr;
        k_gemm_mma<<<gemmGrid, 256, GEMM_SMEM>>>(xin, L, al[L], ar[L], n);
        k_edge<<<(n + 7) / 8, 256>>>(bb[L], hout, n);
    }
}

// round 10
// speedup vs baseline: 1.2379x; 1.0402x over previous
#include <cuda_runtime.h>
#include <cuda_bf16.h>
#include <cuda_fp16.h>
#include <math_constants.h>
#include <cstdint>

#define D 128
#define MAXN 50000
#define MAXE 800000

// -------- scratch (device globals: allocation-free contract) --------
__device__ __half g_z16[MAXN * D];    // projected features (fp16, gather path)
__device__ float g_h[MAXN * D];       // layer output -> next layer input
__device__ float g_el[MAXN];
__device__ float g_er[MAXN];
__device__ float g_e[MAXE];           // per-edge scratch (fallback path only)
__device__ int   g_cnt[MAXN];
__device__ int   g_off[MAXN + 1];
__device__ int   g_woff[MAXN];
__device__ int   g_csr_src[MAXE];
__device__ __nv_bfloat16 g_wh[3][D * D];   // W^T hi split, [n][k] K-major
__device__ __nv_bfloat16 g_wl[3][D * D];   // W^T lo split

// ================= CSR build ================================================

__global__ void k_zcnt(int n) {
    int i = blockIdx.x * blockDim.x + threadIdx.x;
    if (i < n) g_cnt[i] = 0;
}
__global__ void k_hist(const int* __restrict__ dst, int eN) {
    int i = blockIdx.x * blockDim.x + threadIdx.x;
    if (i < eN) atomicAdd(&g_cnt[dst[i]], 1);
}
__global__ __launch_bounds__(1024) void k_scan(int n, int eN) {
    __shared__ int part[1024];
    int t = threadIdx.x;
    int chunk = (n + 1023) / 1024;
    int lo = t * chunk;
    int hi = lo + chunk; if (hi > n) hi = n; if (lo > n) lo = n;
    int s = 0;
    for (int i = lo; i < hi; i++) s += g_cnt[i];
    part[t] = s;
    __syncthreads();
    for (int off = 1; off < 1024; off <<= 1) {
        int v = (t >= off) ? part[t - off] : 0;
        __syncthreads();
        part[t] += v;
        __syncthreads();
    }
    int run = (t == 0) ? 0 : part[t - 1];
    for (int i = lo; i < hi; i++) {
        g_off[i] = run; g_woff[i] = run;
        run += g_cnt[i];
    }
    if (t == 0) g_off[n] = eN;
}
__global__ void k_scatter(const int* __restrict__ src, const int* __restrict__ dst, int eN) {
    int i = blockIdx.x * blockDim.x + threadIdx.x;
    if (i >= eN) return;
    int pos = atomicAdd(&g_woff[dst[i]], 1);
    g_csr_src[pos] = src[i];
}

// ========== W split: W -> W^T bf16 hi/lo, [n][k] K-major (once per layer) ===
__global__ void k_wsplit(const float* __restrict__ W, int L) {
    __shared__ float t[32][33];
    int bx = blockIdx.x, by = blockIdx.y;
    int txx = threadIdx.x, tyy = threadIdx.y;
    t[tyy][txx] = W[(by * 32 + tyy) * D + bx * 32 + txx];
    __syncthreads();
    int n2 = bx * 32 + tyy, k2 = by * 32 + txx;
    float v = t[txx][tyy];
    __nv_bfloat16 hi = __float2bfloat16_rn(v);
    float lo = v - __bfloat162float(hi);
    g_wh[L][n2 * D + k2] = hi;
    g_wl[L][n2 * D + k2] = __float2bfloat16_rn(lo);
}

// ================= mma.sync bf16-split GEMM =================================
__device__ __forceinline__ void mma16816(float* c, uint32_t a0, uint32_t a1,
                                         uint32_t a2, uint32_t a3,
                                         uint32_t b0, uint32_t b1) {
    asm volatile(
        "mma.sync.aligned.m16n8k16.row.col.f32.bf16.bf16.f32 "
        "{%0,%1,%2,%3}, {%4,%5,%6,%7}, {%8,%9}, {%0,%1,%2,%3};"
        : "+f"(c[0]), "+f"(c[1]), "+f"(c[2]), "+f"(c[3])
        : "r"(a0), "r"(a1), "r"(a2), "r"(a3), "r"(b0), "r"(b1));
}
__device__ __forceinline__ uint32_t pack_bf2(float x, float y) {
    __nv_bfloat162 p = __float22bfloat162_rn(make_float2(x, y));
    return *(uint32_t*)&p;
}

#define SMS 136   // padded k-stride (bf16 elems): conflict-free fragment LDS

// z = x@W with fused el/er. CTA: 128 rows x 128 cols, 256 threads, 8 warps.
__global__ __launch_bounds__(256) void k_gemm_mma(const float* __restrict__ xin,
                                                  int L,
                                                  const float* __restrict__ al,
                                                  const float* __restrict__ ar,
                                                  int n) {
    extern __shared__ char smem[];
    __nv_bfloat16* sA0 = (__nv_bfloat16*)smem;          // x hi [128][SMS]
    __nv_bfloat16* sA1 = sA0 + 128 * SMS;               // x lo
    __nv_bfloat16* sB0 = sA1 + 128 * SMS;               // W^T hi
    __nv_bfloat16* sB1 = sB0 + 128 * SMS;               // W^T lo
    float* sal = (float*)(sB1 + 128 * SMS);
    float* sar = sal + 128;

    const float* x = xin ? xin : g_h;
    int tx = threadIdx.x;
    int wid = tx >> 5, lane = tx & 31;
    int row0 = blockIdx.x * 128;

    if (tx < 128) { sal[tx] = al[tx]; sar[tx] = ar[tx]; }

    // ---- fill B ----
    {
        const __nv_bfloat16* wsrc = (tx < 128) ? g_wh[L] : g_wl[L];
        __nv_bfloat16* bd = (tx < 128) ? sB0 : sB1;
        int nn = tx & 127;
        const uint4* sv = (const uint4*)(wsrc + nn * D);
        uint4* dv = (uint4*)(bd + nn * SMS);
#pragma unroll
        for (int i = 0; i < 16; i++) dv[i] = sv[i];
    }
    // ---- fill A: fp32 -> bf16 hi/lo ----
    {
        int row = tx >> 1, h = tx & 1;
        int grow = row0 + row;
        const float4* xr = (const float4*)&x[(size_t)grow * D + h * 64];
#pragma unroll
        for (int j = 0; j < 16; j++) {
            float4 v = (grow < n) ? xr[j] : make_float4(0.f, 0.f, 0.f, 0.f);
            __nv_bfloat16 h0 = __float2bfloat16_rn(v.x);
            __nv_bfloat16 h1 = __float2bfloat16_rn(v.y);
            __nv_bfloat16 h2 = __float2bfloat16_rn(v.z);
            __nv_bfloat16 h3 = __float2bfloat16_rn(v.w);
            uint32_t hp0, hp1;
            { __nv_bfloat162 p = make_bfloat162(h0, h1); hp0 = *(uint32_t*)&p; }
            { __nv_bfloat162 p = make_bfloat162(h2, h3); hp1 = *(uint32_t*)&p; }
            uint32_t lp0 = pack_bf2(v.x - __bfloat162float(h0),
                                    v.y - __bfloat162float(h1));
            uint32_t lp1 = pack_bf2(v.z - __bfloat162float(h2),
                                    v.w - __bfloat162float(h3));
            int ko = h * 64 + j * 4;
            *(uint2*)&sA0[row * SMS + ko] = make_uint2(hp0, hp1);
            *(uint2*)&sA1[row * SMS + ko] = make_uint2(lp0, lp1);
        }
    }
    __syncthreads();

    // ---- compute ----
    int g = lane >> 2, q = lane & 3;
    int ra = wid * 16 + g;
    float acc[16][4];
#pragma unroll
    for (int nt = 0; nt < 16; nt++)
#pragma unroll
        for (int p = 0; p < 4; p++) acc[nt][p] = 0.f;

#pragma unroll
    for (int kc = 0; kc < 8; kc++) {
        int ka = kc * 16 + q * 2;
        uint32_t ah0 = *(const uint32_t*)&sA0[ra * SMS + ka];
        uint32_t ah1 = *(const uint32_t*)&sA0[(ra + 8) * SMS + ka];
        uint32_t ah2 = *(const uint32_t*)&sA0[ra * SMS + ka + 8];
        uint32_t ah3 = *(const uint32_t*)&sA0[(ra + 8) * SMS + ka + 8];
        uint32_t av0 = *(const uint32_t*)&sA1[ra * SMS + ka];
        uint32_t av1 = *(const uint32_t*)&sA1[(ra + 8) * SMS + ka];
        uint32_t av2 = *(const uint32_t*)&sA1[ra * SMS + ka + 8];
        uint32_t av3 = *(const uint32_t*)&sA1[(ra + 8) * SMS + ka + 8];
#pragma unroll
        for (int nt = 0; nt < 16; nt++) {
            int nb = nt * 8 + g;
            uint32_t bh0 = *(const uint32_t*)&sB0[nb * SMS + ka];
            uint32_t bh1 = *(const uint32_t*)&sB0[nb * SMS + ka + 8];
            uint32_t bl0 = *(const uint32_t*)&sB1[nb * SMS + ka];
            uint32_t bl1 = *(const uint32_t*)&sB1[nb * SMS + ka + 8];
            mma16816(acc[nt], ah0, ah1, ah2, ah3, bh0, bh1);   // hi*hi
            mma16816(acc[nt], ah0, ah1, ah2, ah3, bl0, bl1);   // hi*lo
            mma16816(acc[nt], av0, av1, av2, av3, bh0, bh1);   // lo*hi
        }
    }

    // ---- epilogue: z fp16 stores + fused el/er (exact fp32) ----
    int r1 = row0 + ra, r2 = r1 + 8;
    float el1 = 0.f, er1 = 0.f, el2 = 0.f, er2 = 0.f;
#pragma unroll
    for (int nt = 0; nt < 16; nt++) {
        int c0 = nt * 8 + q * 2;
        float a0v = sal[c0], a1v = sal[c0 + 1];
        float r0v = sar[c0], r1v = sar[c0 + 1];
        el1 += acc[nt][0] * a0v + acc[nt][1] * a1v;
        er1 += acc[nt][0] * r0v + acc[nt][1] * r1v;
        el2 += acc[nt][2] * a0v + acc[nt][3] * a1v;
        er2 += acc[nt][2] * r0v + acc[nt][3] * r1v;
        if (r1 < n)
            *(__half2*)&g_z16[(size_t)r1 * D + c0] =
                __floats2half2_rn(acc[nt][0], acc[nt][1]);
        if (r2 < n)
            *(__half2*)&g_z16[(size_t)r2 * D + c0] =
                __floats2half2_rn(acc[nt][2], acc[nt][3]);
    }
#pragma unroll
    for (int o = 1; o <= 2; o <<= 1) {
        el1 += __shfl_xor_sync(0xffffffffu, el1, o);
        er1 += __shfl_xor_sync(0xffffffffu, er1, o);
        el2 += __shfl_xor_sync(0xffffffffu, el2, o);
        er2 += __shfl_xor_sync(0xffffffffu, er2, o);
    }
    if (q == 0) {
        if (r1 < n) { g_el[r1] = el1; g_er[r1] = er1; }
        if (r2 < n) { g_el[r2] = el2; g_er[r2] = er2; }
    }
}

#define GEMM_SMEM (4 * 128 * SMS * 2 + 2 * 128 * 4)

// ---- fp16 row gather helper: lane covers cols [lane*4, lane*4+4) ----
__device__ __forceinline__ void gather_fma(float4& acc, int srow, int lane, float a) {
    uint2 raw = *(const uint2*)&g_z16[(size_t)srow * D + lane * 4];
    float2 f0 = __half22float2(*(__half2*)&raw.x);
    float2 f1 = __half22float2(*(__half2*)&raw.y);
    acc.x = fmaf(a, f0.x, acc.x);
    acc.y = fmaf(a, f0.y, acc.y);
    acc.z = fmaf(a, f1.x, acc.z);
    acc.w = fmaf(a, f1.y, acc.w);
}

// ===== Fused per-dst softmax + aggregate + bias + ReLU (one warp per dst) ===
__global__ __launch_bounds__(256) void k_edge(const float* __restrict__ b,
                                              float* __restrict__ hout, int n) {
    int d = (blockIdx.x * blockDim.x + threadIdx.x) >> 5;
    int lane = threadIdx.x & 31;
    if (d >= n) return;
    int r0 = g_off[d];
    int deg = g_off[d + 1] - r0;
    float4 acc  = make_float4(0.f, 0.f, 0.f, 0.f);
    float4 acc2 = make_float4(0.f, 0.f, 0.f, 0.f);
    float inv = 0.f;

    if (deg > 0 && deg <= 128) {
        float erd = g_er[d];
        int   s[4];
        float ex[4];
        float m = -CUDART_INF_F;
#pragma unroll
        for (int c = 0; c < 4; c++) {
            int idx = c * 32 + lane;
            s[c] = 0; ex[c] = -CUDART_INF_F;
            if (idx < deg) {
                s[c] = g_csr_src[r0 + idx];
                float e = g_el[s[c]] + erd;
                e = e > 0.f ? e : 0.2f * e;
                ex[c] = e;
                m = fmaxf(m, e);
            }
        }
#pragma unroll
        for (int o = 16; o > 0; o >>= 1)
            m = fmaxf(m, __shfl_xor_sync(0xffffffffu, m, o));
        float ssum = 0.f;
#pragma unroll
        for (int c = 0; c < 4; c++) {
            if (c * 32 + lane < deg) {
                ex[c] = __expf(ex[c] - m);
                ssum += ex[c];
            }
        }
#pragma unroll
        for (int o = 16; o > 0; o >>= 1)
            ssum += __shfl_xor_sync(0xffffffffu, ssum, o);
        inv = 1.0f / ssum;
        // gather: 4-way unrolled fp16 row loads, deferred normalization
#pragma unroll
        for (int c = 0; c < 4; c++) {
            if (c * 32 < deg) {
                int lim = deg - c * 32; if (lim > 32) lim = 32;
                int j = 0;
                for (; j + 3 < lim; j += 4) {
                    int   s0 = __shfl_sync(0xffffffffu, s[c], j);
                    float a0 = __shfl_sync(0xffffffffu, ex[c], j);
                    int   s1 = __shfl_sync(0xffffffffu, s[c], j + 1);
                    float a1 = __shfl_sync(0xffffffffu, ex[c], j + 1);
                    int   s2 = __shfl_sync(0xffffffffu, s[c], j + 2);
                    float a2 = __shfl_sync(0xffffffffu, ex[c], j + 2);
                    int   s3 = __shfl_sync(0xffffffffu, s[c], j + 3);
                    float a3 = __shfl_sync(0xffffffffu, ex[c], j + 3);
                    gather_fma(acc,  s0, lane, a0);
                    gather_fma(acc2, s1, lane, a1);
                    gather_fma(acc,  s2, lane, a2);
                    gather_fma(acc2, s3, lane, a3);
                }
                for (; j < lim; j++) {
                    int   s0 = __shfl_sync(0xffffffffu, s[c], j);
                    float a0 = __shfl_sync(0xffffffffu, ex[c], j);
                    gather_fma(acc, s0, lane, a0);
                }
            }
        }
    } else if (deg > 128) {
        float erd = g_er[d];
        float m = -CUDART_INF_F;
        for (int i = lane; i < deg; i += 32) {
            int s = g_csr_src[r0 + i];
            float e = g_el[s] + erd;
            e = e > 0.f ? e : 0.2f * e;
            g_e[r0 + i] = e;
            m = fmaxf(m, e);
        }
#pragma unroll
        for (int o = 16; o > 0; o >>= 1)
            m = fmaxf(m, __shfl_xor_sync(0xffffffffu, m, o));
        float ssum = 0.f;
        for (int i = lane; i < deg; i += 32) {
            float ex = __expf(g_e[r0 + i] - m);
            g_e[r0 + i] = ex;
            ssum += ex;
        }
#pragma unroll
        for (int o = 16; o > 0; o >>= 1)
            ssum += __shfl_xor_sync(0xffffffffu, ssum, o);
        inv = 1.0f / ssum;
        for (int c = 0; c < deg; c += 32) {
            int idx = c + lane;
            int   sl = 0; float exl = 0.f;
            if (idx < deg) { sl = g_csr_src[r0 + idx]; exl = g_e[r0 + idx]; }
            int lim = deg - c; if (lim > 32) lim = 32;
            for (int j = 0; j < lim; j++) {
                int   sj = __shfl_sync(0xffffffffu, sl, j);
                float a  = __shfl_sync(0xffffffffu, exl, j);
                gather_fma(acc, sj, lane, a);
            }
        }
    }
    float4 bv = *(const float4*)&b[lane * 4];
    float4 o;
    o.x = fmaxf(fmaf(acc.x + acc2.x, inv, bv.x), 0.f);
    o.y = fmaxf(fmaf(acc.y + acc2.y, inv, bv.y), 0.f);
    o.z = fmaxf(fmaf(acc.z + acc2.z, inv, bv.z), 0.f);
    o.w = fmaxf(fmaf(acc.w + acc2.w, inv, bv.w), 0.f);
    float* out = hout ? hout : g_h;
    *(float4*)&out[d * D + lane * 4] = o;
}

// -------- launch --------
extern "C" void kernel_launch(void* const* d_in, const int* in_sizes, int n_in,
                              void* d_out, int out_size) {
    const float* f   = (const float*)d_in[0];
    const int*   src = (const int*)d_in[1];
    const int*   dst = (const int*)d_in[2];
    const float* W[3]  = { (const float*)d_in[3], (const float*)d_in[7],  (const float*)d_in[11] };
    const float* al[3] = { (const float*)d_in[4], (const float*)d_in[8],  (const float*)d_in[12] };
    const float* ar[3] = { (const float*)d_in[5], (const float*)d_in[9],  (const float*)d_in[13] };
    const float* bb[3] = { (const float*)d_in[6], (const float*)d_in[10], (const float*)d_in[14] };

    int n  = in_sizes[0] / D;
    int eN = in_sizes[1];
    float* out = (float*)d_out;

    static bool init = false;
    if (!init) {
        cudaFuncSetAttribute(k_gemm_mma, cudaFuncAttributeMaxDynamicSharedMemorySize,
                             GEMM_SMEM);
        init = true;
    }

    // CSR build (graph shared across layers)
    k_zcnt   <<<(n + 255) / 256, 256>>>(n);
    k_hist   <<<(eN + 255) / 256, 256>>>(dst, eN);
    k_scan   <<<1, 1024>>>(n, eN);
    k_scatter<<<(eN + 255) / 256, 256>>>(src, dst, eN);

    // W hi/lo splits
    for (int L = 0; L < 3; L++)
        k_wsplit<<<dim3(4, 4), dim3(32, 32)>>>(W[L], L);

    int gemmGrid = (n + 127) / 128;
    for (int L = 0; L < 3; L++) {
        const float* xin = (L == 0) ? f : nullptr;
        float* hout = (L == 2) ? out : nullptr;
        k_gemm_mma<<<gemmGrid, 256, GEMM_SMEM>>>(xin, L, al[L], ar[L], n);
        k_edge<<<(n + 7) / 8, 256>>>(bb[L], hout, n);
    }
}

// round 12
// speedup vs baseline: 1.3732x; 1.1093x over previous
#include <cuda_runtime.h>
#include <cuda_bf16.h>
#include <cuda_fp16.h>
#include <math_constants.h>
#include <cstdint>

#define D 128
#define MAXN 50000
#define MAXE 800000

// -------- scratch (device globals: allocation-free contract) --------
__device__ __half g_z16[MAXN * D];    // projected features (fp16, gather path)
__device__ float g_h[MAXN * D];       // layer output -> next layer input
__device__ float g_el[MAXN];
__device__ float g_er[MAXN];
__device__ float g_e[MAXE];           // per-edge scratch (fallback path only)
__device__ int   g_cnt[MAXN];
__device__ int   g_off[MAXN + 1];
__device__ int   g_woff[MAXN];
__device__ int   g_csr_src[MAXE];
__device__ __nv_bfloat16 g_wh[3][D * D];   // W^T hi split, [n][k] K-major
__device__ __nv_bfloat16 g_wl[3][D * D];   // W^T lo split

// ================= CSR build ================================================

__global__ void k_hist(const int* __restrict__ dst, int eN) {
    int i = blockIdx.x * blockDim.x + threadIdx.x;
    if (i < eN) atomicAdd(&g_cnt[dst[i]], 1);
}
__global__ __launch_bounds__(1024) void k_scan(int n, int eN) {
    __shared__ int part[1024];
    int t = threadIdx.x;
    int chunk = (n + 1023) / 1024;
    int lo = t * chunk;
    int hi = lo + chunk; if (hi > n) hi = n; if (lo > n) lo = n;
    int s = 0;
    for (int i = lo; i < hi; i++) s += g_cnt[i];
    part[t] = s;
    __syncthreads();
    for (int off = 1; off < 1024; off <<= 1) {
        int v = (t >= off) ? part[t - off] : 0;
        __syncthreads();
        part[t] += v;
        __syncthreads();
    }
    int run = (t == 0) ? 0 : part[t - 1];
    for (int i = lo; i < hi; i++) {
        g_off[i] = run; g_woff[i] = run;
        run += g_cnt[i];
    }
    if (t == 0) g_off[n] = eN;
}
__global__ void k_scatter(const int* __restrict__ src, const int* __restrict__ dst, int eN) {
    int i = blockIdx.x * blockDim.x + threadIdx.x;
    if (i >= eN) return;
    int pos = atomicAdd(&g_woff[dst[i]], 1);
    g_csr_src[pos] = src[i];
}

// ========== W split: W -> W^T bf16 hi/lo, all 3 layers in one launch ========
__global__ void k_wsplit(const float* __restrict__ W0, const float* __restrict__ W1,
                         const float* __restrict__ W2) {
    __shared__ float t[32][33];
    int L = blockIdx.z;
    const float* W = (L == 0) ? W0 : (L == 1) ? W1 : W2;
    int bx = blockIdx.x, by = blockIdx.y;
    int txx = threadIdx.x, tyy = threadIdx.y;
    t[tyy][txx] = W[(by * 32 + tyy) * D + bx * 32 + txx];
    __syncthreads();
    int n2 = bx * 32 + tyy, k2 = by * 32 + txx;
    float v = t[txx][tyy];
    __nv_bfloat16 hi = __float2bfloat16_rn(v);
    float lo = v - __bfloat162float(hi);
    g_wh[L][n2 * D + k2] = hi;
    g_wl[L][n2 * D + k2] = __float2bfloat16_rn(lo);
}

// ================= mma.sync bf16-split GEMM =================================
__device__ __forceinline__ void mma16816(float* c, uint32_t a0, uint32_t a1,
                                         uint32_t a2, uint32_t a3,
                                         uint32_t b0, uint32_t b1) {
    asm volatile(
        "mma.sync.aligned.m16n8k16.row.col.f32.bf16.bf16.f32 "
        "{%0,%1,%2,%3}, {%4,%5,%6,%7}, {%8,%9}, {%0,%1,%2,%3};"
        : "+f"(c[0]), "+f"(c[1]), "+f"(c[2]), "+f"(c[3])
        : "r"(a0), "r"(a1), "r"(a2), "r"(a3), "r"(b0), "r"(b1));
}
__device__ __forceinline__ uint32_t pack_bf2(float x, float y) {
    __nv_bfloat162 p = __float22bfloat162_rn(make_float2(x, y));
    return *(uint32_t*)&p;
}

#define SMS 136   // padded k-stride (bf16 elems): conflict-free fragment LDS

// z = x@W with fused el/er. CTA: 128 rows x 128 cols, 256 threads, 8 warps.
__global__ __launch_bounds__(256) void k_gemm_mma(const float* __restrict__ xin,
                                                  int L,
                                                  const float* __restrict__ al,
                                                  const float* __restrict__ ar,
                                                  int n) {
    extern __shared__ char smem[];
    __nv_bfloat16* sA0 = (__nv_bfloat16*)smem;          // x hi [128][SMS]
    __nv_bfloat16* sA1 = sA0 + 128 * SMS;               // x lo
    __nv_bfloat16* sB0 = sA1 + 128 * SMS;               // W^T hi
    __nv_bfloat16* sB1 = sB0 + 128 * SMS;               // W^T lo
    float* sal = (float*)(sB1 + 128 * SMS);
    float* sar = sal + 128;

    const float* x = xin ? xin : g_h;
    int tx = threadIdx.x;
    int wid = tx >> 5, lane = tx & 31;
    int row0 = blockIdx.x * 128;

    if (tx < 128) { sal[tx] = al[tx]; sar[tx] = ar[tx]; }

    // ---- fill B ----
    {
        const __nv_bfloat16* wsrc = (tx < 128) ? g_wh[L] : g_wl[L];
        __nv_bfloat16* bd = (tx < 128) ? sB0 : sB1;
        int nn = tx & 127;
        const uint4* sv = (const uint4*)(wsrc + nn * D);
        uint4* dv = (uint4*)(bd + nn * SMS);
#pragma unroll
        for (int i = 0; i < 16; i++) dv[i] = sv[i];
    }
    // ---- fill A: fp32 -> bf16 hi/lo ----
    {
        int row = tx >> 1, h = tx & 1;
        int grow = row0 + row;
        const float4* xr = (const float4*)&x[(size_t)grow * D + h * 64];
#pragma unroll
        for (int j = 0; j < 16; j++) {
            float4 v = (grow < n) ? xr[j] : make_float4(0.f, 0.f, 0.f, 0.f);
            __nv_bfloat16 h0 = __float2bfloat16_rn(v.x);
            __nv_bfloat16 h1 = __float2bfloat16_rn(v.y);
            __nv_bfloat16 h2 = __float2bfloat16_rn(v.z);
            __nv_bfloat16 h3 = __float2bfloat16_rn(v.w);
            uint32_t hp0, hp1;
            { __nv_bfloat162 p = make_bfloat162(h0, h1); hp0 = *(uint32_t*)&p; }
            { __nv_bfloat162 p = make_bfloat162(h2, h3); hp1 = *(uint32_t*)&p; }
            uint32_t lp0 = pack_bf2(v.x - __bfloat162float(h0),
                                    v.y - __bfloat162float(h1));
            uint32_t lp1 = pack_bf2(v.z - __bfloat162float(h2),
                                    v.w - __bfloat162float(h3));
            int ko = h * 64 + j * 4;
            *(uint2*)&sA0[row * SMS + ko] = make_uint2(hp0, hp1);
            *(uint2*)&sA1[row * SMS + ko] = make_uint2(lp0, lp1);
        }
    }
    __syncthreads();

    // ---- compute ----
    int g = lane >> 2, q = lane & 3;
    int ra = wid * 16 + g;
    float acc[16][4];
#pragma unroll
    for (int nt = 0; nt < 16; nt++)
#pragma unroll
        for (int p = 0; p < 4; p++) acc[nt][p] = 0.f;

#pragma unroll
    for (int kc = 0; kc < 8; kc++) {
        int ka = kc * 16 + q * 2;
        uint32_t ah0 = *(const uint32_t*)&sA0[ra * SMS + ka];
        uint32_t ah1 = *(const uint32_t*)&sA0[(ra + 8) * SMS + ka];
        uint32_t ah2 = *(const uint32_t*)&sA0[ra * SMS + ka + 8];
        uint32_t ah3 = *(const uint32_t*)&sA0[(ra + 8) * SMS + ka + 8];
        uint32_t av0 = *(const uint32_t*)&sA1[ra * SMS + ka];
        uint32_t av1 = *(const uint32_t*)&sA1[(ra + 8) * SMS + ka];
        uint32_t av2 = *(const uint32_t*)&sA1[ra * SMS + ka + 8];
        uint32_t av3 = *(const uint32_t*)&sA1[(ra + 8) * SMS + ka + 8];
#pragma unroll
        for (int nt = 0; nt < 16; nt++) {
            int nb = nt * 8 + g;
            uint32_t bh0 = *(const uint32_t*)&sB0[nb * SMS + ka];
            uint32_t bh1 = *(const uint32_t*)&sB0[nb * SMS + ka + 8];
            uint32_t bl0 = *(const uint32_t*)&sB1[nb * SMS + ka];
            uint32_t bl1 = *(const uint32_t*)&sB1[nb * SMS + ka + 8];
            mma16816(acc[nt], ah0, ah1, ah2, ah3, bh0, bh1);   // hi*hi
            mma16816(acc[nt], ah0, ah1, ah2, ah3, bl0, bl1);   // hi*lo
            mma16816(acc[nt], av0, av1, av2, av3, bh0, bh1);   // lo*hi
        }
    }

    // ---- epilogue: z fp16 stores + fused el/er (exact fp32) ----
    int r1 = row0 + ra, r2 = r1 + 8;
    float el1 = 0.f, er1 = 0.f, el2 = 0.f, er2 = 0.f;
#pragma unroll
    for (int nt = 0; nt < 16; nt++) {
        int c0 = nt * 8 + q * 2;
        float a0v = sal[c0], a1v = sal[c0 + 1];
        float r0v = sar[c0], r1v = sar[c0 + 1];
        el1 += acc[nt][0] * a0v + acc[nt][1] * a1v;
        er1 += acc[nt][0] * r0v + acc[nt][1] * r1v;
        el2 += acc[nt][2] * a0v + acc[nt][3] * a1v;
        er2 += acc[nt][2] * r0v + acc[nt][3] * r1v;
        if (r1 < n)
            *(__half2*)&g_z16[(size_t)r1 * D + c0] =
                __floats2half2_rn(acc[nt][0], acc[nt][1]);
        if (r2 < n)
            *(__half2*)&g_z16[(size_t)r2 * D + c0] =
                __floats2half2_rn(acc[nt][2], acc[nt][3]);
    }
#pragma unroll
    for (int o = 1; o <= 2; o <<= 1) {
        el1 += __shfl_xor_sync(0xffffffffu, el1, o);
        er1 += __shfl_xor_sync(0xffffffffu, er1, o);
        el2 += __shfl_xor_sync(0xffffffffu, el2, o);
        er2 += __shfl_xor_sync(0xffffffffu, er2, o);
    }
    if (q == 0) {
        if (r1 < n) { g_el[r1] = el1; g_er[r1] = er1; }
        if (r2 < n) { g_el[r2] = el2; g_er[r2] = er2; }
    }
}

#define GEMM_SMEM (4 * 128 * SMS * 2 + 2 * 128 * 4)

// ---- fp16 gather helper (16-lane groups): lane16 covers cols [l*8, l*8+8) --
__device__ __forceinline__ void gather_fma8(float4& a0, float4& a1,
                                            int srow, int lane16, float a) {
    uint4 raw = *(const uint4*)&g_z16[(size_t)srow * D + lane16 * 8];
    float2 f0 = __half22float2(*(__half2*)&raw.x);
    float2 f1 = __half22float2(*(__half2*)&raw.y);
    float2 f2 = __half22float2(*(__half2*)&raw.z);
    float2 f3 = __half22float2(*(__half2*)&raw.w);
    a0.x = fmaf(a, f0.x, a0.x); a0.y = fmaf(a, f0.y, a0.y);
    a0.z = fmaf(a, f1.x, a0.z); a0.w = fmaf(a, f1.y, a0.w);
    a1.x = fmaf(a, f2.x, a1.x); a1.y = fmaf(a, f2.y, a1.y);
    a1.z = fmaf(a, f3.x, a1.z); a1.w = fmaf(a, f3.y, a1.w);
}

// ===== Fused per-dst softmax + aggregate + bias + ReLU =====================
// TWO dsts per warp: each 16-lane group owns one dst node.
__global__ __launch_bounds__(256) void k_edge(const float* __restrict__ b,
                                              float* __restrict__ hout, int n) {
    int tx = threadIdx.x;
    int d = (blockIdx.x * blockDim.x + tx) >> 4;
    int lane16 = tx & 15;
    if (d >= n) return;
    int r0 = g_off[d];
    int deg = g_off[d + 1] - r0;
    float4 accA0 = make_float4(0.f, 0.f, 0.f, 0.f);
    float4 accA1 = make_float4(0.f, 0.f, 0.f, 0.f);
    float4 accB0 = make_float4(0.f, 0.f, 0.f, 0.f);
    float4 accB1 = make_float4(0.f, 0.f, 0.f, 0.f);
    float inv = 0.f;
    const unsigned FM = 0xffffffffu;

    if (deg > 0 && deg <= 64) {
        float erd = g_er[d];
        int   s[4];
        float ex[4];
        float m = -CUDART_INF_F;
#pragma unroll
        for (int c = 0; c < 4; c++) {
            int idx = c * 16 + lane16;
            s[c] = 0; ex[c] = -CUDART_INF_F;
            if (idx < deg) {
                s[c] = g_csr_src[r0 + idx];
                float e = g_el[s[c]] + erd;
                e = e > 0.f ? e : 0.2f * e;
                ex[c] = e;
                m = fmaxf(m, e);
            }
        }
#pragma unroll
        for (int o = 8; o > 0; o >>= 1)
            m = fmaxf(m, __shfl_xor_sync(FM, m, o, 16));
        float ssum = 0.f;
#pragma unroll
        for (int c = 0; c < 4; c++) {
            if (c * 16 + lane16 < deg) {
                ex[c] = __expf(ex[c] - m);
                ssum += ex[c];
            }
        }
#pragma unroll
        for (int o = 8; o > 0; o >>= 1)
            ssum += __shfl_xor_sync(FM, ssum, o, 16);
        inv = 1.0f / ssum;
        // gather: 2-way unrolled, deferred normalization
#pragma unroll
        for (int c = 0; c < 4; c++) {
            if (c * 16 < deg) {
                int lim = deg - c * 16; if (lim > 16) lim = 16;
                int j = 0;
                for (; j + 1 < lim; j += 2) {
                    int   s0 = __shfl_sync(FM, s[c], j, 16);
                    float a0 = __shfl_sync(FM, ex[c], j, 16);
                    int   s1 = __shfl_sync(FM, s[c], j + 1, 16);
                    float a1 = __shfl_sync(FM, ex[c], j + 1, 16);
                    gather_fma8(accA0, accA1, s0, lane16, a0);
                    gather_fma8(accB0, accB1, s1, lane16, a1);
                }
                if (j < lim) {
                    int   s0 = __shfl_sync(FM, s[c], j, 16);
                    float a0 = __shfl_sync(FM, ex[c], j, 16);
                    gather_fma8(accA0, accA1, s0, lane16, a0);
                }
            }
        }
    } else if (deg > 64) {
        // fallback: 3-pass via g_e (rare high-degree nodes), 16 lanes
        float erd = g_er[d];
        float m = -CUDART_INF_F;
        for (int i = lane16; i < deg; i += 16) {
            int s = g_csr_src[r0 + i];
            float e = g_el[s] + erd;
            e = e > 0.f ? e : 0.2f * e;
            g_e[r0 + i] = e;
            m = fmaxf(m, e);
        }
#pragma unroll
        for (int o = 8; o > 0; o >>= 1)
            m = fmaxf(m, __shfl_xor_sync(FM, m, o, 16));
        float ssum = 0.f;
        for (int i = lane16; i < deg; i += 16) {
            float ex = __expf(g_e[r0 + i] - m);
            g_e[r0 + i] = ex;
            ssum += ex;
        }
#pragma unroll
        for (int o = 8; o > 0; o >>= 1)
            ssum += __shfl_xor_sync(FM, ssum, o, 16);
        inv = 1.0f / ssum;
        for (int c = 0; c < deg; c += 16) {
            int idx = c + lane16;
            int   sl = 0; float exl = 0.f;
            if (idx < deg) { sl = g_csr_src[r0 + idx]; exl = g_e[r0 + idx]; }
            int lim = deg - c; if (lim > 16) lim = 16;
            for (int j = 0; j < lim; j++) {
                int   sj = __shfl_sync(FM, sl, j, 16);
                float a  = __shfl_sync(FM, exl, j, 16);
                gather_fma8(accA0, accA1, sj, lane16, a);
            }
        }
    }
    float4 b0 = *(const float4*)&b[lane16 * 8];
    float4 b1 = *(const float4*)&b[lane16 * 8 + 4];
    float4 o0, o1;
    o0.x = fmaxf(fmaf(accA0.x + accB0.x, inv, b0.x), 0.f);
    o0.y = fmaxf(fmaf(accA0.y + accB0.y, inv, b0.y), 0.f);
    o0.z = fmaxf(fmaf(accA0.z + accB0.z, inv, b0.z), 0.f);
    o0.w = fmaxf(fmaf(accA0.w + accB0.w, inv, b0.w), 0.f);
    o1.x = fmaxf(fmaf(accA1.x + accB1.x, inv, b1.x), 0.f);
    o1.y = fmaxf(fmaf(accA1.y + accB1.y, inv, b1.y), 0.f);
    o1.z = fmaxf(fmaf(accA1.z + accB1.z, inv, b1.z), 0.f);
    o1.w = fmaxf(fmaf(accA1.w + accB1.w, inv, b1.w), 0.f);
    float* out = hout ? hout : g_h;
    *(float4*)&out[(size_t)d * D + lane16 * 8]     = o0;
    *(float4*)&out[(size_t)d * D + lane16 * 8 + 4] = o1;
}

// -------- launch --------
extern "C" void kernel_launch(void* const* d_in, const int* in_sizes, int n_in,
                              void* d_out, int out_size) {
    const float* f   = (const float*)d_in[0];
    const int*   src = (const int*)d_in[1];
    const int*   dst = (const int*)d_in[2];
    const float* W[3]  = { (const float*)d_in[3], (const float*)d_in[7],  (const float*)d_in[11] };
    const float* al[3] = { (const float*)d_in[4], (const float*)d_in[8],  (const float*)d_in[12] };
    const float* ar[3] = { (const float*)d_in[5], (const float*)d_in[9],  (const float*)d_in[13] };
    const float* bb[3] = { (const float*)d_in[6], (const float*)d_in[10], (const float*)d_in[14] };

    int n  = in_sizes[0] / D;
    int eN = in_sizes[1];
    float* out = (float*)d_out;

    static cudaStream_t s2 = nullptr;
    static cudaEvent_t evFork = nullptr, evJoin = nullptr;
    static void* cntPtr = nullptr;
    if (!s2) {
        cudaStreamCreateWithFlags(&s2, cudaStreamNonBlocking);
        cudaEventCreateWithFlags(&evFork, cudaEventDisableTiming);
        cudaEventCreateWithFlags(&evJoin, cudaEventDisableTiming);
        cudaGetSymbolAddress(&cntPtr, g_cnt);
        cudaFuncSetAttribute(k_gemm_mma, cudaFuncAttributeMaxDynamicSharedMemorySize,
                             GEMM_SMEM);
    }

    // Fork: CSR build on s2, overlapped with wsplit + layer-1 GEMM.
    cudaEventRecord(evFork, 0);
    cudaStreamWaitEvent(s2, evFork, 0);
    cudaMemsetAsync(cntPtr, 0, (size_t)n * sizeof(int), s2);
    k_hist   <<<(eN + 255) / 256, 256, 0, s2>>>(dst, eN);
    k_scan   <<<1, 1024, 0, s2>>>(n, eN);
    k_scatter<<<(eN + 255) / 256, 256, 0, s2>>>(src, dst, eN);
    cudaEventRecord(evJoin, s2);

    // W hi/lo splits (all layers, one launch) + layer-1 GEMM on main stream
    k_wsplit<<<dim3(4, 4, 3), dim3(32, 32)>>>(W[0], W[1], W[2]);

    int gemmGrid = (n + 127) / 128;
    k_gemm_mma<<<gemmGrid, 256, GEMM_SMEM>>>(f, 0, al[0], ar[0], n);

    cudaStreamWaitEvent(0, evJoin, 0);

    int edgeGrid = (n + 15) / 16;
    k_edge<<<edgeGrid, 256>>>(bb[0], nullptr, n);

    for (int L = 1; L < 3; L++) {
        float* hout = (L == 2) ? out : nullptr;
        k_gemm_mma<<<gemmGrid, 256, GEMM_SMEM>>>(nullptr, L, al[L], ar[L], n);
        k_edge<<<edgeGrid, 256>>>(bb[L], hout, n);
    }
}